// round 5
// baseline (speedup 1.0000x reference)
#include <cuda_runtime.h>
#include <mma.h>

using namespace nvcuda;

#define EDIM   2048
#define NHEADS 16
#define DHEAD  128
#define NBATCH 4
#define SEQ    2048
#define MROWS  (NBATCH * SEQ)   // 8192

// ---------------- scratch (no allocs allowed) ----------------
__device__ float g_q[16777216];   // (N*H, S, D)
__device__ float g_k[16777216];
__device__ float g_v[16777216];
__device__ float g_o[16777216];   // (N*S, E)

// =================================================================
// TF32 GEMM:  C[M=8192, N=2048] = A[M,E] @ W[N,E]^T   (no bias)
// permuted=1 -> write C to (batch, head, s, d) layout for attention
// =================================================================
#define BK 32
#define LDA 40   // 32 + 8 pad, float4-aligned

__global__ __launch_bounds__(256) void gemm_at_kernel(
    const float* __restrict__ A, const float* __restrict__ W,
    float* __restrict__ out, int permuted)
{
    __shared__ float As[128 * LDA];
    __shared__ float Bs[128 * LDA];

    const int tid  = threadIdx.x;
    const int warp = tid >> 5;
    const int m0 = blockIdx.y * 128;
    const int n0 = blockIdx.x * 128;
    const int wr = warp >> 2;   // 0..1  (row group of 64)
    const int wc = warp & 3;    // 0..3  (col group of 32)

    wmma::fragment<wmma::accumulator, 16, 16, 8, float> acc[4][2];
#pragma unroll
    for (int i = 0; i < 4; i++)
#pragma unroll
        for (int j = 0; j < 2; j++)
            wmma::fill_fragment(acc[i][j], 0.0f);

    for (int k0 = 0; k0 < EDIM; k0 += BK) {
        // load A tile 128x32 (1024 float4)
#pragma unroll
        for (int i = tid; i < 1024; i += 256) {
            int r = i >> 3, c = (i & 7) * 4;
            float4 v = *(const float4*)(A + (size_t)(m0 + r) * EDIM + k0 + c);
            *(float4*)(As + r * LDA + c) = v;
        }
        // load W tile: rows n0..n0+127, cols k0..k0+31
#pragma unroll
        for (int i = tid; i < 1024; i += 256) {
            int r = i >> 3, c = (i & 7) * 4;
            float4 v = *(const float4*)(W + (size_t)(n0 + r) * EDIM + k0 + c);
            *(float4*)(Bs + r * LDA + c) = v;
        }
        __syncthreads();

#pragma unroll
        for (int kk = 0; kk < BK / 8; kk++) {
            wmma::fragment<wmma::matrix_a, 16, 16, 8, wmma::precision::tf32, wmma::row_major> af[4];
            wmma::fragment<wmma::matrix_b, 16, 16, 8, wmma::precision::tf32, wmma::col_major> bf[2];
#pragma unroll
            for (int i = 0; i < 4; i++) {
                wmma::load_matrix_sync(af[i], As + (wr * 64 + i * 16) * LDA + kk * 8, LDA);
#pragma unroll
                for (int e = 0; e < af[i].num_elements; e++)
                    af[i].x[e] = wmma::__float_to_tf32(af[i].x[e]);
            }
#pragma unroll
            for (int j = 0; j < 2; j++) {
                wmma::load_matrix_sync(bf[j], Bs + (wc * 32 + j * 16) * LDA + kk * 8, LDA);
#pragma unroll
                for (int e = 0; e < bf[j].num_elements; e++)
                    bf[j].x[e] = wmma::__float_to_tf32(bf[j].x[e]);
            }
#pragma unroll
            for (int i = 0; i < 4; i++)
#pragma unroll
                for (int j = 0; j < 2; j++)
                    wmma::mma_sync(acc[i][j], af[i], bf[j], acc[i][j]);
        }
        __syncthreads();
    }

#pragma unroll
    for (int i = 0; i < 4; i++) {
#pragma unroll
        for (int j = 0; j < 2; j++) {
            int row = m0 + wr * 64 + i * 16;
            int col = n0 + wc * 32 + j * 16;
            if (permuted) {
                int b = row >> 11, s = row & 2047;
                int h = col >> 7,  dc = col & 127;
                wmma::store_matrix_sync(
                    out + ((size_t)(b * NHEADS + h) * SEQ + s) * DHEAD + dc,
                    acc[i][j], DHEAD, wmma::mem_row_major);
            } else {
                wmma::store_matrix_sync(out + (size_t)row * EDIM + col,
                                        acc[i][j], EDIM, wmma::mem_row_major);
            }
        }
    }
}

// =================================================================
// Flash attention: per (batch,head), 64-query tile, stream 64-key tiles
// scores[t,s] = q_s . k_t * (1/sqrt(128)), softmax over t, O = P @ V
// =================================================================
#define LDQ 132  // 128 + 4
#define LDS 68   // 64 + 4
#define FLASH_SMEM ((5 * 64 * LDQ + 64 * LDS + 128) * 4)  // 186880 B

__global__ __launch_bounds__(256) void flash_kernel(
    const int* __restrict__ mask,
    const float* __restrict__ bq, const float* __restrict__ bk,
    const float* __restrict__ bv)
{
    extern __shared__ float sm[];
    float* Qs  = sm;                 // 64 x LDQ
    float* Ks  = Qs  + 64 * LDQ;
    float* Vs  = Ks  + 64 * LDQ;
    float* Os  = Vs  + 64 * LDQ;
    float* PVs = Os  + 64 * LDQ;
    float* Ss  = PVs + 64 * LDQ;     // 64 x LDS
    float* alpha_s = Ss + 64 * LDS;  // 64
    float* l_s     = alpha_s + 64;   // 64

    const int tid  = threadIdx.x;
    const int warp = tid >> 5;
    const int q0   = blockIdx.x * 64;
    const int nh   = blockIdx.y;
    const int bat  = nh / NHEADS;
    const int h    = nh % NHEADS;

    const float* Qg = g_q + ((size_t)nh * SEQ + q0) * DHEAD;
    const float* Kg = g_k + (size_t)nh * SEQ * DHEAD;
    const float* Vg = g_v + (size_t)nh * SEQ * DHEAD;

    // load Q tile (+bias), zero O accumulator
#pragma unroll
    for (int i = tid; i < 2048; i += 256) {
        int r = i >> 5, c = (i & 31) * 4;
        float4 v = *(const float4*)(Qg + (size_t)r * DHEAD + c);
        float4 b = *(const float4*)(bq + h * DHEAD + c);
        v.x += b.x; v.y += b.y; v.z += b.z; v.w += b.w;
        *(float4*)(Qs + r * LDQ + c) = v;
    }
#pragma unroll
    for (int i = tid; i < 64 * LDQ; i += 256) Os[i] = 0.0f;

    const int   q   = tid >> 2;
    const int   sub = tid & 3;
    float m_prev = -INFINITY;
    float l_run  = 0.0f;
    const float scale = 0.08838834764831845f;  // 1/sqrt(128)

    for (int t0 = 0; t0 < SEQ; t0 += 64) {
        // load K,V tiles (+bias)
#pragma unroll
        for (int i = tid; i < 2048; i += 256) {
            int r = i >> 5, c = (i & 31) * 4;
            float4 kv = *(const float4*)(Kg + ((size_t)(t0 + r)) * DHEAD + c);
            float4 bb = *(const float4*)(bk + h * DHEAD + c);
            kv.x += bb.x; kv.y += bb.y; kv.z += bb.z; kv.w += bb.w;
            *(float4*)(Ks + r * LDQ + c) = kv;
            float4 vv = *(const float4*)(Vg + ((size_t)(t0 + r)) * DHEAD + c);
            float4 bv4 = *(const float4*)(bv + h * DHEAD + c);
            vv.x += bv4.x; vv.y += bv4.y; vv.z += bv4.z; vv.w += bv4.w;
            *(float4*)(Vs + r * LDQ + c) = vv;
        }
        __syncthreads();

        // S[q,t] = Q @ K^T   (64x64, K-dim 128)
        {
            const int rb = warp & 3;   // row block
            const int cp = warp >> 2;  // col pair
            wmma::fragment<wmma::accumulator, 16, 16, 8, float> c[2];
            wmma::fill_fragment(c[0], 0.0f);
            wmma::fill_fragment(c[1], 0.0f);
#pragma unroll
            for (int kk = 0; kk < 16; kk++) {
                wmma::fragment<wmma::matrix_a, 16, 16, 8, wmma::precision::tf32, wmma::row_major> a;
                wmma::load_matrix_sync(a, Qs + rb * 16 * LDQ + kk * 8, LDQ);
#pragma unroll
                for (int e = 0; e < a.num_elements; e++) a.x[e] = wmma::__float_to_tf32(a.x[e]);
#pragma unroll
                for (int j = 0; j < 2; j++) {
                    wmma::fragment<wmma::matrix_b, 16, 16, 8, wmma::precision::tf32, wmma::col_major> b;
                    wmma::load_matrix_sync(b, Ks + (cp * 32 + j * 16) * LDQ + kk * 8, LDQ);
#pragma unroll
                    for (int e = 0; e < b.num_elements; e++) b.x[e] = wmma::__float_to_tf32(b.x[e]);
                    wmma::mma_sync(c[j], a, b, c[j]);
                }
            }
#pragma unroll
            for (int j = 0; j < 2; j++)
                wmma::store_matrix_sync(Ss + rb * 16 * LDS + cp * 32 + j * 16, c[j],
                                        LDS, wmma::mem_row_major);
        }
        __syncthreads();

        // online softmax (rows = queries, reduce over keys t)
        float vals[16];
        float mloc = -INFINITY;
#pragma unroll
        for (int j = 0; j < 16; j++) {
            int t = sub + j * 4;
            float v = Ss[q * LDS + t];
            int mv = mask[(size_t)(t0 + t) * SEQ + (q0 + q)];
            v = mv ? v * scale : -INFINITY;
            vals[j] = v;
            mloc = fmaxf(mloc, v);
        }
        mloc = fmaxf(mloc, __shfl_xor_sync(0xffffffffu, mloc, 1));
        mloc = fmaxf(mloc, __shfl_xor_sync(0xffffffffu, mloc, 2));
        float m_new = fmaxf(m_prev, mloc);
        float al = (m_prev == -INFINITY) ? 0.0f : __expf(m_prev - m_new);
        float ps = 0.0f;
#pragma unroll
        for (int j = 0; j < 16; j++) {
            float p = (vals[j] == -INFINITY) ? 0.0f : __expf(vals[j] - m_new);
            Ss[q * LDS + sub + j * 4] = p;
            ps += p;
        }
        ps += __shfl_xor_sync(0xffffffffu, ps, 1);
        ps += __shfl_xor_sync(0xffffffffu, ps, 2);
        l_run = l_run * al + ps;
        m_prev = m_new;
        if (sub == 0) alpha_s[q] = al;
        __syncthreads();

        // PV = P[64,64] @ V[64,128]
        {
            const int rb = warp >> 1;
            const int cg = warp & 1;
            wmma::fragment<wmma::accumulator, 16, 16, 8, float> c[4];
#pragma unroll
            for (int j = 0; j < 4; j++) wmma::fill_fragment(c[j], 0.0f);
#pragma unroll
            for (int kk = 0; kk < 8; kk++) {
                wmma::fragment<wmma::matrix_a, 16, 16, 8, wmma::precision::tf32, wmma::row_major> a;
                wmma::load_matrix_sync(a, Ss + rb * 16 * LDS + kk * 8, LDS);
#pragma unroll
                for (int e = 0; e < a.num_elements; e++) a.x[e] = wmma::__float_to_tf32(a.x[e]);
#pragma unroll
                for (int j = 0; j < 4; j++) {
                    wmma::fragment<wmma::matrix_b, 16, 16, 8, wmma::precision::tf32, wmma::row_major> b;
                    wmma::load_matrix_sync(b, Vs + kk * 8 * LDQ + cg * 64 + j * 16, LDQ);
#pragma unroll
                    for (int e = 0; e < b.num_elements; e++) b.x[e] = wmma::__float_to_tf32(b.x[e]);
                    wmma::mma_sync(c[j], a, b, c[j]);
                }
            }
#pragma unroll
            for (int j = 0; j < 4; j++)
                wmma::store_matrix_sync(PVs + rb * 16 * LDQ + cg * 64 + j * 16, c[j],
                                        LDQ, wmma::mem_row_major);
        }
        __syncthreads();

        // O = O * alpha + PV
#pragma unroll
        for (int i = tid; i < 64 * 128; i += 256) {
            int qq = i >> 7, dv = i & 127;
            Os[qq * LDQ + dv] = Os[qq * LDQ + dv] * alpha_s[qq] + PVs[qq * LDQ + dv];
        }
        __syncthreads();
    }

    if (sub == 0) l_s[q] = l_run;
    __syncthreads();

    // write O / l to (N,S,E) layout
#pragma unroll
    for (int i = tid; i < 64 * 128; i += 256) {
        int qq = i >> 7, dv = i & 127;
        float l = l_s[qq];
        float o = (l > 0.0f) ? Os[qq * LDQ + dv] / l : 0.0f;
        g_o[((size_t)bat * SEQ + q0 + qq) * EDIM + h * DHEAD + dv] = o;
    }
}

// final bias add
__global__ void bias_add_kernel(float* __restrict__ out, const float* __restrict__ bp)
{
    size_t i = (size_t)blockIdx.x * 256 + threadIdx.x;
    if (i < (size_t)MROWS * EDIM) out[i] += bp[i & (EDIM - 1)];
}

// =================================================================
extern "C" void kernel_launch(void* const* d_in, const int* in_sizes, int n_in,
                              void* d_out, int out_size)
{
    const float* query = (const float*)d_in[0];
    const float* key   = (const float*)d_in[1];
    const float* value = (const float*)d_in[2];
    const int*   mask  = (const int*)d_in[3];
    const float* Wq = (const float*)d_in[4];
    const float* bq = (const float*)d_in[5];
    const float* Wk = (const float*)d_in[6];
    const float* bk = (const float*)d_in[7];
    const float* Wv = (const float*)d_in[8];
    const float* bv = (const float*)d_in[9];
    const float* Wp = (const float*)d_in[10];
    const float* bp = (const float*)d_in[11];
    float* out = (float*)d_out;

    float *pq, *pk, *pv, *po;
    cudaGetSymbolAddress((void**)&pq, g_q);
    cudaGetSymbolAddress((void**)&pk, g_k);
    cudaGetSymbolAddress((void**)&pv, g_v);
    cudaGetSymbolAddress((void**)&po, g_o);

    cudaFuncSetAttribute(flash_kernel, cudaFuncAttributeMaxDynamicSharedMemorySize,
                         FLASH_SMEM);

    dim3 gg(EDIM / 128, MROWS / 128);   // (16, 64)
    gemm_at_kernel<<<gg, 256>>>(query, Wq, pq, 1);
    gemm_at_kernel<<<gg, 256>>>(key,   Wk, pk, 1);
    gemm_at_kernel<<<gg, 256>>>(value, Wv, pv, 1);

    dim3 gf(SEQ / 64, NBATCH * NHEADS);  // (32, 64)
    flash_kernel<<<gf, 256, FLASH_SMEM>>>(mask, bq, bk, bv);

    gemm_at_kernel<<<gg, 256>>>(po, Wp, out, 0);

    bias_add_kernel<<<(unsigned)(((size_t)MROWS * EDIM + 255) / 256), 256>>>(out, bp);
}